// round 8
// baseline (speedup 1.0000x reference)
#include <cuda_runtime.h>
#include <cuda_fp16.h>
#include <mma.h>
#include <cstdint>

using namespace nvcuda;

// ---------------- Problem constants ----------------
#define B_DIM 16
#define T_DIM 8192
#define H_DIM 256
#define N_TOT 512
#define TILE_M 128
#define TILE_N 128            // output cols per CTA; n0 = (blockIdx.x&1)*128
#define KC 64
#define NCHUNKS 4
#define N_TILES 1024
#define TILES_PER_BATCH 64
#define TPB 256               // 8 warps, warp tile 64x32 (dual GEMM)
#define Q_TILES 14            // tiles per CTA pair (74*14 = 1036 >= 1024)
#define NROWS_TOTAL (B_DIM * T_DIM)

// ---------------- SMEM layout: 2-stage ring + dedicated epilogue ----------------
#define PITCH_K 72                                  // fp16 elems/row (144 B)
#define A_BYTES (TILE_M * PITCH_K * 2)              // 18432
#define B_BYTES (256 * PITCH_K * 2)                 // 36864
#define STAGE_BYTES (A_BYTES + B_BYTES)             // 55296
#define OFF_A_S(s) ((s) * STAGE_BYTES)
#define OFF_B_S(s) ((s) * STAGE_BYTES + A_BYTES)
#define PITCH_E 68
#define OFF_S1 (2 * STAGE_BYTES)                    // 110592
#define OFF_S2 (OFF_S1 + TILE_M * PITCH_E * 4)      // +34816
#define SMEM_TOTAL (OFF_S2 + TILE_M * PITCH_E * 4)  // 180224

// ---------------- Device scratch ----------------
__device__ __half g_Wf[N_TOT * H_DIM];
__device__ float g_edge[(size_t)N_TILES * 8 * H_DIM];

__device__ __forceinline__ uint32_t smem_u32(const void* p){
    uint32_t a;
    asm("{ .reg .u64 t; cvta.to.shared.u64 t, %1; cvt.u32.u64 %0, t; }" : "=r"(a) : "l"(p));
    return a;
}
__device__ __forceinline__ void cp16(void* dst, const void* src){
    uint32_t d = smem_u32(dst);
    asm volatile("cp.async.cg.shared.global [%0], [%1], 16;" :: "r"(d), "l"(src) : "memory");
}
__device__ __forceinline__ void cp_commit(){ asm volatile("cp.async.commit_group;" ::: "memory"); }
template<int N> __device__ __forceinline__ void cp_wait(){ asm volatile("cp.async.wait_group %0;" :: "n"(N) : "memory"); }

// ============ kernel 0: weights -> fp16 ============
__global__ void fsmn_convw_kernel(const float* __restrict__ Wlin, const float* __restrict__ Wmem){
    int r = blockIdx.x, k = threadIdx.x;
    float w = (r < 256) ? Wlin[r * H_DIM + k] : Wmem[(r - 256) * H_DIM + k];
    g_Wf[r * H_DIM + k] = __float2half(w);
}

// ============ main kernel helpers ============
// B chunk (tile-invariant): 256 rows x 64 fp16 = 2048 x 16B, 8/thread, 1 commit group
__device__ __forceinline__ void load_B_async(char* smem, int slot, int c, int n0, int tid){
    #pragma unroll
    for (int it = 0; it < 8; it++){
        int idx = tid + it * TPB;
        int row = idx >> 3;
        int j   = idx & 7;
        int grow = (row < 128) ? (n0 + row) : (128 + n0 + row);
        cp16(smem + OFF_B_S(slot) + row * (PITCH_K * 2) + j * 16,
             g_Wf + (size_t)grow * H_DIM + c * KC + j * 8);
    }
    cp_commit();
}
// A chunk: fp32 LDG (32 floats/thread), held in regs
__device__ __forceinline__ void ldg_A(float4* v, const float* __restrict__ x,
                                      int tile, int c, int tid){
    int row  = tid >> 1;
    int colb = (tid & 1) * 32;
    const float* src = x + (size_t)(tile * TILE_M + row) * H_DIM + c * KC + colb;
    #pragma unroll
    for (int q = 0; q < 8; q++)
        v[q] = *reinterpret_cast<const float4*>(src + q * 4);
}
// convert + store A chunk to smem (fp16, PITCH_K layout)
__device__ __forceinline__ void sts_A(char* smem, int slot, const float4* v, int tid){
    int row  = tid >> 1;
    int colb = (tid & 1) * 64;    // bytes (32 halfs)
    char* dst = smem + OFF_A_S(slot) + row * (PITCH_K * 2) + colb;
    #pragma unroll
    for (int q = 0; q < 4; q++){
        __half2 a = __floats2half2_rn(v[2*q].x,   v[2*q].y);
        __half2 b = __floats2half2_rn(v[2*q].z,   v[2*q].w);
        __half2 e = __floats2half2_rn(v[2*q+1].x, v[2*q+1].y);
        __half2 d = __floats2half2_rn(v[2*q+1].z, v[2*q+1].w);
        uint4 p;
        p.x = *reinterpret_cast<uint32_t*>(&a);
        p.y = *reinterpret_cast<uint32_t*>(&b);
        p.z = *reinterpret_cast<uint32_t*>(&e);
        p.w = *reinterpret_cast<uint32_t*>(&d);
        *reinterpret_cast<uint4*>(dst + q * 16) = p;
    }
}

// ============ main persistent kernel ============
__global__ void __launch_bounds__(TPB, 1)
fsmn_main_kernel(const float* __restrict__ x,
                 const float* __restrict__ b_lin,
                 const float* __restrict__ b_mem,
                 float* __restrict__ out){
    extern __shared__ char smem[];
    const int tid  = threadIdx.x;
    const int wid  = tid >> 5;
    const int warp_m = wid >> 2;          // 0..1 -> rows warp_m*64
    const int warp_n = wid & 3;           // 0..3 -> cols warp_n*32
    const int n0   = (blockIdx.x & 1) * TILE_N;
    const int pair = blockIdx.x >> 1;
    const int t_begin = pair * Q_TILES;
    const int t_end   = (t_begin + Q_TILES < N_TILES) ? (t_begin + Q_TILES) : N_TILES;
    if (t_begin >= N_TILES) return;
    const int G = (t_end - t_begin) * NCHUNKS;   // total chunks (>= 8)

    const int mrow = warp_m * 64;
    const int ncol = warp_n * 32;

    float4 av[8];

    // prologue: chunks 0,1 (A via LDG+STS, B via cp.async; one group per chunk)
    ldg_A(av, x, t_begin, 0, tid);
    sts_A(smem, 0, av, tid);
    load_B_async(smem, 0, 0, n0, tid);
    ldg_A(av, x, t_begin, 1, tid);
    sts_A(smem, 1, av, tid);
    load_B_async(smem, 1, 1, n0, tid);
    int next_issue = 2;
    int g = 0;

    for (int t = t_begin; t < t_end; t++){
        wmma::fragment<wmma::accumulator, 16, 16, 16, float> acc1[4][2], acc2[4][2];
        #pragma unroll
        for (int m4 = 0; m4 < 4; m4++)
            #pragma unroll
            for (int n2 = 0; n2 < 2; n2++){
                wmma::fill_fragment(acc1[m4][n2], 0.0f);
                wmma::fill_fragment(acc2[m4][n2], 0.0f);
            }

        #pragma unroll
        for (int c = 0; c < NCHUNKS; c++, g++){
            if (g == G - 1) cp_wait<0>(); else cp_wait<1>();
            __syncthreads();               // chunk g (A sts + B cp.async) visible

            // prefetch A for chunk g+2 into regs (hidden under compute)
            bool do_issue = (next_issue < G);
            if (do_issue)
                ldg_A(av, x, t_begin + (next_issue >> 2), next_issue & 3, tid);

            char* S = smem + OFF_A_S(g & 1);        // slot base
            __half* A  = reinterpret_cast<__half*>(S);
            __half* Bm = reinterpret_cast<__half*>(smem + OFF_B_S(g & 1));

            #pragma unroll
            for (int kk = 0; kk < 4; kk++){
                wmma::fragment<wmma::matrix_b, 16, 16, 16, __half, wmma::col_major> b1[2], b2[2];
                #pragma unroll
                for (int n2 = 0; n2 < 2; n2++){
                    wmma::load_matrix_sync(b1[n2], Bm + (ncol + n2 * 16) * PITCH_K + kk * 16, PITCH_K);
                    wmma::load_matrix_sync(b2[n2], Bm + (128 + ncol + n2 * 16) * PITCH_K + kk * 16, PITCH_K);
                }
                #pragma unroll
                for (int m4 = 0; m4 < 4; m4++){
                    wmma::fragment<wmma::matrix_a, 16, 16, 16, __half, wmma::row_major> a;
                    wmma::load_matrix_sync(a, A + (mrow + m4 * 16) * PITCH_K + kk * 16, PITCH_K);
                    #pragma unroll
                    for (int n2 = 0; n2 < 2; n2++){
                        wmma::mma_sync(acc1[m4][n2], a, b1[n2], acc1[m4][n2]);
                        wmma::mma_sync(acc2[m4][n2], a, b2[n2], acc2[m4][n2]);
                    }
                }
            }
            __syncthreads();               // slot (g&1) free for reuse
            if (do_issue){
                int slot = next_issue & 1;
                sts_A(smem, slot, av, tid);
                load_B_async(smem, slot, next_issue & 3, n0, tid);
                next_issue++;
            }
        }

        // ================= epilogue (tile t) =================
        float* S1 = reinterpret_cast<float*>(smem + OFF_S1);
        float* S2 = reinterpret_cast<float*>(smem + OFF_S2);
        const int row_base = t * TILE_M;
        const int first_tile = ((t & (TILES_PER_BATCH - 1)) == 0);
        const int col = tid & 63;
        const int rg  = tid >> 6;          // 0..3 -> rows rg*32..+31

        #pragma unroll
        for (int h = 0; h < 2; h++){
            __syncthreads();
            if ((warp_n >> 1) == h){
                int cbase = (warp_n & 1) * 32;
                #pragma unroll
                for (int m4 = 0; m4 < 4; m4++)
                    #pragma unroll
                    for (int n2 = 0; n2 < 2; n2++){
                        wmma::store_matrix_sync(S1 + (mrow + m4 * 16) * PITCH_E + cbase + n2 * 16,
                                                acc1[m4][n2], PITCH_E, wmma::mem_row_major);
                        wmma::store_matrix_sync(S2 + (mrow + m4 * 16) * PITCH_E + cbase + n2 * 16,
                                                acc2[m4][n2], PITCH_E, wmma::mem_row_major);
                    }
            }
            __syncthreads();

            int gcol = n0 + h * 64 + col;
            float bsum = b_lin[gcol] + b_mem[gcol];
            int r0 = rg * 32;
            float sum8 = 0.f;
            #pragma unroll
            for (int d = 1; d <= 8; d++){
                int rr = r0 - d;
                if (rr >= 0) sum8 += S2[rr * PITCH_E + col];
            }
            #pragma unroll
            for (int i = 0; i < 32; i++){
                int r = r0 + i;
                float cur  = S2[r * PITCH_E + col];
                float wsum = sum8 + cur;
                float inv  = (first_tile && r < 8) ? (1.f / (float)(r + 1)) : (1.f / 9.f);
                out[(size_t)(row_base + r) * H_DIM + gcol] = S1[r * PITCH_E + col] + bsum + wsum * inv;
                if (r >= 120)
                    g_edge[((size_t)t * 8 + (r - 120)) * H_DIM + gcol] = cur;
                float drop = (r >= 8) ? S2[(r - 8) * PITCH_E + col] : 0.f;
                sum8 += cur - drop;
            }
        }
        __syncthreads();   // epilogue fully done before accs reused next tile
    }
}

// ============ kernel 2: patch cross-tile window contributions ============
__global__ void fsmn_fix_kernel(float* __restrict__ out){
    int bid = blockIdx.x;
    int b  = bid / (TILES_PER_BATCH - 1);
    int jt = bid % (TILES_PER_BATCH - 1) + 1;
    int prev_tile = b * TILES_PER_BATCH + jt - 1;
    int n = threadIdx.x;
    const float* e = &g_edge[(size_t)prev_tile * 8 * H_DIM];
    size_t obase = (size_t)(b * TILES_PER_BATCH + jt) * TILE_M * H_DIM;
    float suf = 0.f;
    #pragma unroll
    for (int jr = 7; jr >= 0; jr--){
        suf += e[jr * H_DIM + n];
        out[obase + (size_t)jr * H_DIM + n] += suf * (1.f / 9.f);
    }
}

// ============ launch ============
extern "C" void kernel_launch(void* const* d_in, const int* in_sizes, int n_in,
                              void* d_out, int out_size){
    const float* x     = (const float*)d_in[0];
    const float* W_lin = (const float*)d_in[1];
    const float* b_lin = (const float*)d_in[2];
    const float* W_mem = (const float*)d_in[3];
    const float* b_mem = (const float*)d_in[4];
    float* out = (float*)d_out;

    cudaFuncSetAttribute(fsmn_main_kernel, cudaFuncAttributeMaxDynamicSharedMemorySize, SMEM_TOTAL);

    fsmn_convw_kernel<<<N_TOT, H_DIM>>>(W_lin, W_mem);
    fsmn_main_kernel<<<148, TPB, SMEM_TOTAL>>>(x, b_lin, b_mem, out);
    fsmn_fix_kernel<<<B_DIM * (TILES_PER_BATCH - 1), H_DIM>>>(out);
}